// round 1
// baseline (speedup 1.0000x reference)
#include <cuda_runtime.h>
#include <math.h>

#define BQ    2
#define TT    1024
#define HIDD  2048
#define NH    16
#define DKD   128
#define DVD   128
#define MROWS 2048   // BQ*TT

// ---------------- scratch (device globals; no allocation allowed) ----------
__device__ float g_qpre[MROWS * HIDD];
__device__ float g_kpre[MROWS * HIDD];
__device__ float g_vpre[MROWS * HIDD];
__device__ float g_q[MROWS * HIDD];
__device__ float g_k[MROWS * HIDD];
__device__ float g_v[MROWS * HIDD];
__device__ float g_egf[MROWS * HIDD];   // g_base -> exp(gate_fast)
__device__ float g_egs[MROWS * HIDD];   // g_delta -> exp(gate_slow)
__device__ float g_gbp[MROWS * 128];
__device__ float g_gdp[MROWS * 128];
__device__ float g_g1p[MROWS * 128];
__device__ float g_gate[MROWS * HIDD];
__device__ float g_bf[MROWS * NH];
__device__ float g_bs[MROWS * NH];
__device__ float g_lm[MROWS * NH];
__device__ float g_ost[2 * MROWS * HIDD];
__device__ float g_omix[MROWS * HIDD];

// ---------------- fp32 tiled GEMM: C[M,N] = A[M,K] @ B[K,N] (+bias) --------
// BM=BN=128, BK=16, 256 threads, 8x8 per-thread tile.
// Requires M%128==0, N%128==0, K%16==0.
__global__ __launch_bounds__(256, 2)
void sgemm_nn(const float* __restrict__ A, const float* __restrict__ Bm,
              float* __restrict__ C, int M, int N, int K,
              const float* __restrict__ bias)
{
    __shared__ float As[16][128];
    __shared__ float Bs[16][128];
    const int tid = threadIdx.x;
    const int bm  = blockIdx.y * 128;
    const int bn  = blockIdx.x * 128;
    const int tx  = tid & 15;          // 0..15 -> 8 cols each
    const int ty  = tid >> 4;          // 0..15 -> 8 rows each

    float acc[8][8];
#pragma unroll
    for (int i = 0; i < 8; i++)
#pragma unroll
        for (int j = 0; j < 8; j++) acc[i][j] = 0.f;

    const int am  = tid >> 1;          // 0..127
    const int ak  = (tid & 1) * 8;     // 0 or 8
    const int bk  = tid >> 4;          // 0..15
    const int bn8 = (tid & 15) * 8;    // 0..120

    for (int k0 = 0; k0 < K; k0 += 16) {
        const float* Ap = A + (size_t)(bm + am) * K + k0 + ak;
        float4 a0 = *(const float4*)(Ap);
        float4 a1 = *(const float4*)(Ap + 4);
        As[ak + 0][am] = a0.x; As[ak + 1][am] = a0.y;
        As[ak + 2][am] = a0.z; As[ak + 3][am] = a0.w;
        As[ak + 4][am] = a1.x; As[ak + 5][am] = a1.y;
        As[ak + 6][am] = a1.z; As[ak + 7][am] = a1.w;

        const float* Bp = Bm + (size_t)(k0 + bk) * N + bn + bn8;
        *(float4*)&Bs[bk][bn8]     = *(const float4*)(Bp);
        *(float4*)&Bs[bk][bn8 + 4] = *(const float4*)(Bp + 4);
        __syncthreads();

#pragma unroll
        for (int kk = 0; kk < 16; kk++) {
            float af[8], bf[8];
            *(float4*)&af[0] = *(float4*)&As[kk][ty * 8];
            *(float4*)&af[4] = *(float4*)&As[kk][ty * 8 + 4];
            *(float4*)&bf[0] = *(float4*)&Bs[kk][tx * 8];
            *(float4*)&bf[4] = *(float4*)&Bs[kk][tx * 8 + 4];
#pragma unroll
            for (int i = 0; i < 8; i++)
#pragma unroll
                for (int j = 0; j < 8; j++)
                    acc[i][j] += af[i] * bf[j];
        }
        __syncthreads();
    }

#pragma unroll
    for (int i = 0; i < 8; i++) {
        int row = bm + ty * 8 + i;
        float* Cp = C + (size_t)row * N + bn + tx * 8;
        if (bias) {
#pragma unroll
            for (int j = 0; j < 8; j++) acc[i][j] += bias[bn + tx * 8 + j];
        }
        *(float4*)Cp       = make_float4(acc[i][0], acc[i][1], acc[i][2], acc[i][3]);
        *(float4*)(Cp + 4) = make_float4(acc[i][4], acc[i][5], acc[i][6], acc[i][7]);
    }
}

// 64x64 variant for skinny N (N=128): better grid parallelism.
__global__ __launch_bounds__(256)
void sgemm_nn64(const float* __restrict__ A, const float* __restrict__ Bm,
                float* __restrict__ C, int M, int N, int K)
{
    __shared__ float As[16][64];
    __shared__ float Bs[16][64];
    const int tid = threadIdx.x;
    const int bm  = blockIdx.y * 64;
    const int bn  = blockIdx.x * 64;
    const int tx  = tid & 15;
    const int ty  = tid >> 4;

    float acc[4][4];
#pragma unroll
    for (int i = 0; i < 4; i++)
#pragma unroll
        for (int j = 0; j < 4; j++) acc[i][j] = 0.f;

    const int am  = tid >> 2;         // 0..63
    const int ak  = (tid & 3) * 4;    // 0..12
    const int bk  = tid >> 4;         // 0..15
    const int bn4 = (tid & 15) * 4;

    for (int k0 = 0; k0 < K; k0 += 16) {
        float4 a0 = *(const float4*)(A + (size_t)(bm + am) * K + k0 + ak);
        As[ak + 0][am] = a0.x; As[ak + 1][am] = a0.y;
        As[ak + 2][am] = a0.z; As[ak + 3][am] = a0.w;
        *(float4*)&Bs[bk][bn4] = *(const float4*)(Bm + (size_t)(k0 + bk) * N + bn + bn4);
        __syncthreads();
#pragma unroll
        for (int kk = 0; kk < 16; kk++) {
            float af[4], bf[4];
            *(float4*)af = *(float4*)&As[kk][ty * 4];
            *(float4*)bf = *(float4*)&Bs[kk][tx * 4];
#pragma unroll
            for (int i = 0; i < 4; i++)
#pragma unroll
                for (int j = 0; j < 4; j++)
                    acc[i][j] += af[i] * bf[j];
        }
        __syncthreads();
    }
#pragma unroll
    for (int i = 0; i < 4; i++) {
        float* Cp = C + (size_t)(bm + ty * 4 + i) * N + bn + tx * 4;
        *(float4*)Cp = make_float4(acc[i][0], acc[i][1], acc[i][2], acc[i][3]);
    }
}

// ---------------- bb/bd/lam raw dot products (N=16 skinny) -----------------
__global__ void beta_dots(const float* __restrict__ x,
                          const float* __restrict__ Wbb,
                          const float* __restrict__ Wbd,
                          const float* __restrict__ Wlam,
                          float* __restrict__ bf, float* __restrict__ bs,
                          float* __restrict__ lm)
{
    __shared__ float xs[HIDD];
    const int row = blockIdx.x;
    const float* xr = x + (size_t)row * HIDD;
    for (int i = threadIdx.x; i < HIDD; i += 256) xs[i] = xr[i];
    __syncthreads();

    const int w    = threadIdx.x >> 5;
    const int lane = threadIdx.x & 31;
    for (int d = w; d < 48; d += 8) {
        const int mat = d >> 4, h = d & 15;
        const float* W = (mat == 0) ? Wbb : ((mat == 1) ? Wbd : Wlam);
        float s = 0.f;
        for (int i = lane; i < HIDD; i += 32) s += xs[i] * W[(size_t)i * NH + h];
#pragma unroll
        for (int off = 16; off; off >>= 1) s += __shfl_xor_sync(0xffffffffu, s, off);
        if (lane == 0) {
            float* dst = (mat == 0) ? bf : ((mat == 1) ? bs : lm);
            dst[row * NH + h] = s;
        }
    }
}

// sigmoid-combine: bf=sig(bb+bd), bs=sig(bb-bd), lm=sig(lm)
__global__ void beta_sig(float* bf, float* bs, float* lm, int n)
{
    int i = blockIdx.x * 256 + threadIdx.x;
    if (i >= n) return;
    float bb = bf[i], bd = bs[i], l = lm[i];
    bf[i] = 1.f / (1.f + expf(-(bb + bd)));
    bs[i] = 1.f / (1.f + expf(-(bb - bd)));
    lm[i] = 1.f / (1.f + expf(-l));
}

// ---------------- causal depthwise conv(4) + SiLU (+ per-head l2norm) ------
__global__ void conv_silu_norm(const float* __restrict__ qpre,
                               const float* __restrict__ kpre,
                               const float* __restrict__ vpre,
                               const float* __restrict__ cwq,
                               const float* __restrict__ cwk,
                               const float* __restrict__ cwv,
                               float* __restrict__ qo, float* __restrict__ ko,
                               float* __restrict__ vo)
{
    const int z = blockIdx.z;
    const float* pre = (z == 0) ? qpre : ((z == 1) ? kpre : vpre);
    const float* cw  = (z == 0) ? cwq  : ((z == 1) ? cwk  : cwv);
    float* out       = (z == 0) ? qo   : ((z == 1) ? ko   : vo);

    const int row = blockIdx.x;          // b*TT + t
    const int h   = blockIdx.y;
    const int t   = row & (TT - 1);
    const int c   = h * DKD + threadIdx.x;
    const size_t base = (size_t)row * HIDD + c;

    const float w0 = cw[c * 4 + 0], w1 = cw[c * 4 + 1];
    const float w2 = cw[c * 4 + 2], w3 = cw[c * 4 + 3];

    float y = w3 * pre[base];
    if (t >= 1) y += w2 * pre[base - HIDD];
    if (t >= 2) y += w1 * pre[base - 2 * HIDD];
    if (t >= 3) y += w0 * pre[base - 3 * HIDD];
    y = y / (1.f + expf(-y));            // SiLU

    if (z < 2) {                          // l2norm over head dim (128)
        __shared__ float red[4];
        float ss = y * y;
#pragma unroll
        for (int off = 16; off; off >>= 1) ss += __shfl_xor_sync(0xffffffffu, ss, off);
        if ((threadIdx.x & 31) == 0) red[threadIdx.x >> 5] = ss;
        __syncthreads();
        float tot = red[0] + red[1] + red[2] + red[3];
        float r = rsqrtf(tot + 1e-6f);
        if (z == 0) r *= 0.08838834764831845f;  // fold q scale DK^-0.5
        y *= r;
    }
    out[base] = y;
}

// ---------------- decay gates: eg = exp(-exp(A)*softplus(g +/- gd + dtb)) --
__global__ void gates_kernel(const float* __restrict__ A_log,
                             const float* __restrict__ dt_bias,
                             float* __restrict__ egf, float* __restrict__ egs)
{
    int idx = blockIdx.x * 256 + threadIdx.x;
    if (idx >= MROWS * HIDD) return;
    int c = idx & (HIDD - 1);
    int h = c >> 7;
    float gb = egf[idx], gd = egs[idx];
    float A  = expf(A_log[h]);
    float db = dt_bias[c];
    float xf = gb + gd + db, xs = gb - gd + db;
    float spf = (xf > 20.f) ? xf : log1pf(expf(xf));
    float sps = (xs > 20.f) ? xs : log1pf(expf(xs));
    egf[idx] = expf(-A * spf);
    egs[idx] = expf(-A * sps);
}

// ---------------- dual-state gated delta-rule recurrence -------------------
// Columns of S over DV are independent. grid(4 vblocks, 16 heads, 4 s*b).
// 128 threads: tid = vloc*4 + sub; sub owns 32 dk rows of column v.
__global__ __launch_bounds__(128)
void recurrence_kernel(const float* __restrict__ q, const float* __restrict__ k,
                       const float* __restrict__ v,
                       const float* __restrict__ egf, const float* __restrict__ egs,
                       const float* __restrict__ bfa, const float* __restrict__ bsa,
                       float* __restrict__ ost)
{
    const int s  = blockIdx.z >> 1;
    const int b  = blockIdx.z & 1;
    const int h  = blockIdx.y;
    const int vb = blockIdx.x;
    const int tid  = threadIdx.x;
    const int vloc = tid >> 2;
    const int sub  = tid & 3;
    const int vcol = vb * 32 + vloc;
    const int dk0  = sub * 32;

    const size_t rowbase = (size_t)b * TT * HIDD + h * DKD;
    const float* kp  = k   + rowbase + dk0;
    const float* qp  = q   + rowbase + dk0;
    const float* egp = ((s == 0) ? egf : egs) + rowbase + dk0;
    const float* vp  = v   + rowbase + vcol;
    const float* bp  = ((s == 0) ? bfa : bsa) + (size_t)b * TT * NH + h;
    float* op = ost + (size_t)s * MROWS * HIDD + rowbase + vcol;

    float S[32];
#pragma unroll
    for (int i = 0; i < 32; i++) S[i] = 0.f;

    for (int t = 0; t < TT; t++) {
        const size_t off = (size_t)t * HIDD;
        float kreg[32];
        float m0 = 0.f, m1 = 0.f, m2 = 0.f, m3 = 0.f;
#pragma unroll
        for (int i = 0; i < 32; i += 4) {
            float4 k4 = *(const float4*)(kp + off + i);
            float4 e4 = *(const float4*)(egp + off + i);
            float s0 = S[i + 0] * e4.x; S[i + 0] = s0;
            float s1 = S[i + 1] * e4.y; S[i + 1] = s1;
            float s2 = S[i + 2] * e4.z; S[i + 2] = s2;
            float s3 = S[i + 3] * e4.w; S[i + 3] = s3;
            kreg[i + 0] = k4.x; kreg[i + 1] = k4.y;
            kreg[i + 2] = k4.z; kreg[i + 3] = k4.w;
            m0 += k4.x * s0; m1 += k4.y * s1;
            m2 += k4.z * s2; m3 += k4.w * s3;
        }
        float mem = (m0 + m1) + (m2 + m3);
        mem += __shfl_xor_sync(0xffffffffu, mem, 1);
        mem += __shfl_xor_sync(0xffffffffu, mem, 2);

        const float beta = bp[(size_t)t * NH];
        const float vt   = vp[off];
        const float u    = beta * (vt - mem);

        float o0 = 0.f, o1 = 0.f, o2 = 0.f, o3 = 0.f;
#pragma unroll
        for (int i = 0; i < 32; i += 4) {
            float4 q4 = *(const float4*)(qp + off + i);
            float s0 = S[i + 0] + kreg[i + 0] * u; S[i + 0] = s0;
            float s1 = S[i + 1] + kreg[i + 1] * u; S[i + 1] = s1;
            float s2 = S[i + 2] + kreg[i + 2] * u; S[i + 2] = s2;
            float s3 = S[i + 3] + kreg[i + 3] * u; S[i + 3] = s3;
            o0 += q4.x * s0; o1 += q4.y * s1;
            o2 += q4.z * s2; o3 += q4.w * s3;
        }
        float o = (o0 + o1) + (o2 + o3);
        o += __shfl_xor_sync(0xffffffffu, o, 1);
        o += __shfl_xor_sync(0xffffffffu, o, 2);
        if (sub == 0) op[off] = o;
    }
}

// ---------------- mix + gated RMSNorm --------------------------------------
__global__ void combine_kernel(const float* __restrict__ ost,
                               const float* __restrict__ lm,
                               const float* __restrict__ gate,
                               const float* __restrict__ onw,
                               float* __restrict__ omix)
{
    const int row = blockIdx.x;
    const int h   = blockIdx.y;
    const int dv  = threadIdx.x;
    const size_t i0 = (size_t)row * HIDD + h * DKD + dv;

    float of = ost[i0];
    float os = ost[(size_t)MROWS * HIDD + i0];
    float l  = lm[row * NH + h];
    float o  = l * of + (1.f - l) * os;

    __shared__ float red[4];
    float ss = o * o;
#pragma unroll
    for (int off = 16; off; off >>= 1) ss += __shfl_xor_sync(0xffffffffu, ss, off);
    if ((threadIdx.x & 31) == 0) red[threadIdx.x >> 5] = ss;
    __syncthreads();
    float tot = red[0] + red[1] + red[2] + red[3];
    float r = rsqrtf(tot * (1.f / 128.f) + 1e-5f);

    o = o * r * onw[dv];
    float g = gate[i0];
    o = o / (1.f + expf(-g));
    omix[i0] = o;
}

// ---------------- launch ---------------------------------------------------
extern "C" void kernel_launch(void* const* d_in, const int* in_sizes, int n_in,
                              void* d_out, int out_size)
{
    (void)in_sizes; (void)n_in; (void)out_size;
    const float* x    = (const float*)d_in[0];
    const float* Wq   = (const float*)d_in[1];
    const float* Wk   = (const float*)d_in[2];
    const float* Wv   = (const float*)d_in[3];
    const float* cwq  = (const float*)d_in[4];
    const float* cwk  = (const float*)d_in[5];
    const float* cwv  = (const float*)d_in[6];
    const float* Wgb1 = (const float*)d_in[7];
    const float* Wgb2 = (const float*)d_in[8];
    const float* Wgd1 = (const float*)d_in[9];
    const float* Wgd2 = (const float*)d_in[10];
    const float* Wbb  = (const float*)d_in[11];
    const float* Wbd  = (const float*)d_in[12];
    const float* Wlam = (const float*)d_in[13];
    const float* A_log= (const float*)d_in[14];
    const float* dtb  = (const float*)d_in[15];
    const float* Wg1  = (const float*)d_in[16];
    const float* Wg2  = (const float*)d_in[17];
    const float* bg2  = (const float*)d_in[18];
    const float* onw  = (const float*)d_in[19];
    const float* Wo   = (const float*)d_in[20];
    float* out = (float*)d_out;

    float *qpre, *kpre, *vpre, *q, *k, *v, *egf, *egs;
    float *gbp, *gdp, *g1p, *gate, *bf, *bs, *lm, *ost, *omix;
    cudaGetSymbolAddress((void**)&qpre, g_qpre);
    cudaGetSymbolAddress((void**)&kpre, g_kpre);
    cudaGetSymbolAddress((void**)&vpre, g_vpre);
    cudaGetSymbolAddress((void**)&q,    g_q);
    cudaGetSymbolAddress((void**)&k,    g_k);
    cudaGetSymbolAddress((void**)&v,    g_v);
    cudaGetSymbolAddress((void**)&egf,  g_egf);
    cudaGetSymbolAddress((void**)&egs,  g_egs);
    cudaGetSymbolAddress((void**)&gbp,  g_gbp);
    cudaGetSymbolAddress((void**)&gdp,  g_gdp);
    cudaGetSymbolAddress((void**)&g1p,  g_g1p);
    cudaGetSymbolAddress((void**)&gate, g_gate);
    cudaGetSymbolAddress((void**)&bf,   g_bf);
    cudaGetSymbolAddress((void**)&bs,   g_bs);
    cudaGetSymbolAddress((void**)&lm,   g_lm);
    cudaGetSymbolAddress((void**)&ost,  g_ost);
    cudaGetSymbolAddress((void**)&omix, g_omix);

    dim3 g16(16, 16);
    // projections
    sgemm_nn<<<g16, 256>>>(x, Wq, qpre, MROWS, HIDD, HIDD, nullptr);
    sgemm_nn<<<g16, 256>>>(x, Wk, kpre, MROWS, HIDD, HIDD, nullptr);
    sgemm_nn<<<g16, 256>>>(x, Wv, vpre, MROWS, HIDD, HIDD, nullptr);
    // low-rank stage 1 (N=128)
    dim3 gsk(2, 32);
    sgemm_nn64<<<gsk, 256>>>(x, Wgb1, gbp, MROWS, 128, HIDD);
    sgemm_nn64<<<gsk, 256>>>(x, Wgd1, gdp, MROWS, 128, HIDD);
    sgemm_nn64<<<gsk, 256>>>(x, Wg1,  g1p, MROWS, 128, HIDD);
    // low-rank stage 2 (K=128)
    sgemm_nn<<<g16, 256>>>(gbp, Wgb2, egf,  MROWS, HIDD, 128, nullptr);
    sgemm_nn<<<g16, 256>>>(gdp, Wgd2, egs,  MROWS, HIDD, 128, nullptr);
    sgemm_nn<<<g16, 256>>>(g1p, Wg2,  gate, MROWS, HIDD, 128, bg2);
    // betas / lambda
    beta_dots<<<MROWS, 256>>>(x, Wbb, Wbd, Wlam, bf, bs, lm);
    beta_sig<<<(MROWS * NH + 255) / 256, 256>>>(bf, bs, lm, MROWS * NH);
    // conv + silu (+ l2norm for q,k)
    conv_silu_norm<<<dim3(MROWS, NH, 3), 128>>>(qpre, kpre, vpre, cwq, cwk, cwv, q, k, v);
    // decay gates -> exp form
    gates_kernel<<<(MROWS * HIDD) / 256, 256>>>(A_log, dtb, egf, egs);
    // recurrence (both states)
    recurrence_kernel<<<dim3(4, NH, 4), 128>>>(q, k, v, egf, egs, bf, bs, ost);
    // mix + gated rmsnorm
    combine_kernel<<<dim3(MROWS, NH), 128>>>(ost, lm, gate, onw, omix);
    // output projection
    sgemm_nn<<<g16, 256>>>(omix, Wo, out, MROWS, HIDD, HIDD, nullptr);
}

// round 3
// speedup vs baseline: 1.4689x; 1.4689x over previous
#include <cuda_runtime.h>
#include <cuda_bf16.h>
#include <math.h>
#include <stdint.h>

#define BQ    2
#define TT    1024
#define HIDD  2048
#define NH    16
#define DKD   128
#define DVD   128
#define MROWS 2048   // BQ*TT

// =================== scratch (device globals; no allocation) ===============
__device__ __align__(16) float g_qpre[MROWS * HIDD];
__device__ __align__(16) float g_kpre[MROWS * HIDD];
__device__ __align__(16) float g_vpre[MROWS * HIDD];
__device__ __align__(16) float g_q[MROWS * HIDD];
__device__ __align__(16) float g_k[MROWS * HIDD];
__device__ __align__(16) float g_v[MROWS * HIDD];
__device__ __align__(16) float g_egf[MROWS * HIDD];
__device__ __align__(16) float g_egs[MROWS * HIDD];
__device__ __align__(16) float g_gbp[MROWS * 128];
__device__ __align__(16) float g_gdp[MROWS * 128];
__device__ __align__(16) float g_g1p[MROWS * 128];
__device__ __align__(16) float g_gate[MROWS * HIDD];
__device__ __align__(16) float g_bf[MROWS * NH];
__device__ __align__(16) float g_bs[MROWS * NH];
__device__ __align__(16) float g_lm[MROWS * NH];
__device__ __align__(16) float g_ost[2 * MROWS * HIDD];
__device__ __align__(16) float g_omix[MROWS * HIDD];

// bf16 hi/lo splits
__device__ __align__(16) __nv_bfloat16 g_xh[MROWS * HIDD];
__device__ __align__(16) __nv_bfloat16 g_xl[MROWS * HIDD];
__device__ __align__(16) __nv_bfloat16 g_oh[MROWS * HIDD];
__device__ __align__(16) __nv_bfloat16 g_ol[MROWS * HIDD];
__device__ __align__(16) __nv_bfloat16 g_p1h[3][MROWS * 128];
__device__ __align__(16) __nv_bfloat16 g_p1l[3][MROWS * 128];
// transposed weights [N,K] hi/lo
__device__ __align__(16) __nv_bfloat16 g_WqkvTh[3][HIDD * HIDD];
__device__ __align__(16) __nv_bfloat16 g_WqkvTl[3][HIDD * HIDD];
__device__ __align__(16) __nv_bfloat16 g_WoTh[HIDD * HIDD];
__device__ __align__(16) __nv_bfloat16 g_WoTl[HIDD * HIDD];
__device__ __align__(16) __nv_bfloat16 g_W1Th[3][128 * HIDD];
__device__ __align__(16) __nv_bfloat16 g_W1Tl[3][128 * HIDD];
__device__ __align__(16) __nv_bfloat16 g_W2Th[3][HIDD * 128];
__device__ __align__(16) __nv_bfloat16 g_W2Tl[3][HIDD * 128];

// =================== warp-MMA primitives (baseline PTX, sm_80+) ===========
__device__ __forceinline__ void mma16816(float* c, const uint32_t* a, const uint32_t* b) {
    asm volatile(
        "mma.sync.aligned.m16n8k16.row.col.f32.bf16.bf16.f32 "
        "{%0,%1,%2,%3}, {%4,%5,%6,%7}, {%8,%9}, {%0,%1,%2,%3};"
        : "+f"(c[0]), "+f"(c[1]), "+f"(c[2]), "+f"(c[3])
        : "r"(a[0]), "r"(a[1]), "r"(a[2]), "r"(a[3]), "r"(b[0]), "r"(b[1]));
}
__device__ __forceinline__ void ldsm_x4(uint32_t* r, uint32_t addr) {
    asm volatile("ldmatrix.sync.aligned.m8n8.x4.shared.b16 {%0,%1,%2,%3}, [%4];"
                 : "=r"(r[0]), "=r"(r[1]), "=r"(r[2]), "=r"(r[3]) : "r"(addr));
}

// =================== compensated-bf16 HMMA GEMM ============================
// C[z] = A[z][M,K] @ B[z][N,K]^T, A/B bf16 hi+lo, C fp32.
// Block 128x128x32; 8 warps, warp tile 64x32; 3 passes: AhBh + AhBl + AlBh.
struct TcArgs {
    const __nv_bfloat16 *Ah[3], *Al[3], *Bh[3], *Bl[3];
    float *C[3];
    const float *bias[3];
    int M, N, K;
};

#define TSTRIDE 40   // 32 + 8 pad: 80B rows -> ldmatrix conflict-free (5r mod 8)

__global__ void __launch_bounds__(256, 2) hmma_gemm(const TcArgs args)
{
    __shared__ __nv_bfloat16 Ah_s[128 * TSTRIDE];
    __shared__ __nv_bfloat16 Al_s[128 * TSTRIDE];
    __shared__ __nv_bfloat16 Bh_s[128 * TSTRIDE];
    __shared__ __nv_bfloat16 Bl_s[128 * TSTRIDE];

    const int tid  = threadIdx.x;
    const int wid  = tid >> 5, lane = tid & 31;
    const int wm   = wid >> 2;          // 0..1 -> 64 rows
    const int wn   = wid & 3;           // 0..3 -> 32 cols
    const int z    = blockIdx.z;
    const int bm   = blockIdx.y * 128, bn = blockIdx.x * 128;
    const int K    = args.K;
    const __nv_bfloat16* Ah = args.Ah[z];
    const __nv_bfloat16* Al = args.Al[z];
    const __nv_bfloat16* Bh = args.Bh[z];
    const __nv_bfloat16* Bl = args.Bl[z];

    const uint32_t AhU = (uint32_t)__cvta_generic_to_shared(Ah_s);
    const uint32_t AlU = (uint32_t)__cvta_generic_to_shared(Al_s);
    const uint32_t BhU = (uint32_t)__cvta_generic_to_shared(Bh_s);
    const uint32_t BlU = (uint32_t)__cvta_generic_to_shared(Bl_s);

    float C[4][4][4];
#pragma unroll
    for (int i = 0; i < 4; i++)
#pragma unroll
        for (int j = 0; j < 4; j++)
#pragma unroll
            for (int e = 0; e < 4; e++) C[i][j][e] = 0.f;

    // ldmatrix fragment addresses (bf16-element offsets, x2 for bytes)
    const int a_r = (lane & 15);
    const int a_c = (lane >> 4) << 3;
    const int b_r = (lane & 7) + ((lane >> 4) << 3);
    const int b_c = ((lane >> 3) & 1) << 3;

    for (int k0 = 0; k0 < K; k0 += 32) {
        __syncthreads();
#pragma unroll
        for (int u = 0; u < 2; u++) {
            const int ch  = tid + u * 256;       // 0..511
            const int row = ch >> 2, c16 = (ch & 3) * 8;
            const size_t ga = (size_t)(bm + row) * K + k0 + c16;
            const size_t gb = (size_t)(bn + row) * K + k0 + c16;
            const int so = row * TSTRIDE + c16;
            *(uint4*)&Ah_s[so] = *(const uint4*)(Ah + ga);
            *(uint4*)&Al_s[so] = *(const uint4*)(Al + ga);
            *(uint4*)&Bh_s[so] = *(const uint4*)(Bh + gb);
            *(uint4*)&Bl_s[so] = *(const uint4*)(Bl + gb);
        }
        __syncthreads();

#pragma unroll
        for (int pass = 0; pass < 3; pass++) {
            const uint32_t AsU = (pass == 2) ? AlU : AhU;
            const uint32_t BsU = (pass == 1) ? BlU : BhU;
#pragma unroll
            for (int kk = 0; kk < 32; kk += 16) {
                uint32_t af[4][4], bfr[2][4];
#pragma unroll
                for (int mi = 0; mi < 4; mi++) {
                    const int r = wm * 64 + mi * 16 + a_r;
                    ldsm_x4(af[mi], AsU + (uint32_t)(r * TSTRIDE + kk + a_c) * 2);
                }
#pragma unroll
                for (int nb = 0; nb < 2; nb++) {
                    const int r = wn * 32 + nb * 16 + b_r;
                    ldsm_x4(bfr[nb], BsU + (uint32_t)(r * TSTRIDE + kk + b_c) * 2);
                }
#pragma unroll
                for (int mi = 0; mi < 4; mi++)
#pragma unroll
                    for (int nj = 0; nj < 4; nj++)
                        mma16816(C[mi][nj], af[mi], &bfr[nj >> 1][(nj & 1) * 2]);
            }
        }
    }

    // epilogue
    float* Cg = args.C[z];
    const float* bias = args.bias[z];
    const int N = args.N;
#pragma unroll
    for (int mi = 0; mi < 4; mi++) {
#pragma unroll
        for (int nj = 0; nj < 4; nj++) {
            const int r0 = bm + wm * 64 + mi * 16 + (lane >> 2);
            const int c0 = bn + wn * 32 + nj * 8 + (lane & 3) * 2;
            float v0 = C[mi][nj][0], v1 = C[mi][nj][1];
            float v2 = C[mi][nj][2], v3 = C[mi][nj][3];
            if (bias) {
                const float b0 = bias[c0], b1 = bias[c0 + 1];
                v0 += b0; v1 += b1; v2 += b0; v3 += b1;
            }
            *(float2*)(Cg + (size_t)r0 * N + c0)       = make_float2(v0, v1);
            *(float2*)(Cg + (size_t)(r0 + 8) * N + c0) = make_float2(v2, v3);
        }
    }
}

// =================== hi/lo split (elementwise) =============================
__global__ void convert_hilo(const float* __restrict__ s,
                             __nv_bfloat16* __restrict__ h,
                             __nv_bfloat16* __restrict__ l, int n)
{
    int i = (blockIdx.x * 256 + threadIdx.x) * 4;
    if (i >= n) return;
    float4 v = *(const float4*)(s + i);
    __nv_bfloat16 h0 = __float2bfloat16(v.x), h1 = __float2bfloat16(v.y);
    __nv_bfloat16 h2 = __float2bfloat16(v.z), h3 = __float2bfloat16(v.w);
    __nv_bfloat162 hh0; hh0.x = h0; hh0.y = h1;
    __nv_bfloat162 hh1; hh1.x = h2; hh1.y = h3;
    *(__nv_bfloat162*)(h + i)     = hh0;
    *(__nv_bfloat162*)(h + i + 2) = hh1;
    __nv_bfloat162 ll0, ll1;
    ll0.x = __float2bfloat16(v.x - __bfloat162float(h0));
    ll0.y = __float2bfloat16(v.y - __bfloat162float(h1));
    ll1.x = __float2bfloat16(v.z - __bfloat162float(h2));
    ll1.y = __float2bfloat16(v.w - __bfloat162float(h3));
    *(__nv_bfloat162*)(l + i)     = ll0;
    *(__nv_bfloat162*)(l + i + 2) = ll1;
}

// =================== transpose + hi/lo split: W[K,N] -> Bt[N,K] ============
struct TrArgs {
    const float* src[3];
    __nv_bfloat16 *dh[3], *dl[3];
    int K, N;   // src shape
};
__global__ void transpose_hilo(const TrArgs a)
{
    __shared__ float tile[32][33];
    const float* W = a.src[blockIdx.z];
    __nv_bfloat16* dh = a.dh[blockIdx.z];
    __nv_bfloat16* dl = a.dl[blockIdx.z];
    const int n0 = blockIdx.x * 32, k0 = blockIdx.y * 32;
    const int tx = threadIdx.x, ty = threadIdx.y;
#pragma unroll
    for (int i = 0; i < 32; i += 8)
        tile[ty + i][tx] = W[(size_t)(k0 + ty + i) * a.N + n0 + tx];
    __syncthreads();
#pragma unroll
    for (int i = 0; i < 32; i += 8) {
        float v = tile[tx][ty + i];
        __nv_bfloat16 h = __float2bfloat16(v);
        size_t o = (size_t)(n0 + ty + i) * a.K + k0 + tx;
        dh[o] = h;
        dl[o] = __float2bfloat16(v - __bfloat162float(h));
    }
}

// =================== bb/bd/lam skinny dots =================================
__global__ void beta_dots(const float* __restrict__ x,
                          const float* __restrict__ Wbb,
                          const float* __restrict__ Wbd,
                          const float* __restrict__ Wlam,
                          float* __restrict__ bf, float* __restrict__ bs,
                          float* __restrict__ lm)
{
    __shared__ float xs[HIDD];
    const int row = blockIdx.x;
    const float* xr = x + (size_t)row * HIDD;
    for (int i = threadIdx.x; i < HIDD; i += 256) xs[i] = xr[i];
    __syncthreads();
    const int w = threadIdx.x >> 5, lane = threadIdx.x & 31;
    for (int d = w; d < 48; d += 8) {
        const int mat = d >> 4, h = d & 15;
        const float* W = (mat == 0) ? Wbb : ((mat == 1) ? Wbd : Wlam);
        float s = 0.f;
        for (int i = lane; i < HIDD; i += 32) s += xs[i] * W[(size_t)i * NH + h];
#pragma unroll
        for (int off = 16; off; off >>= 1) s += __shfl_xor_sync(0xffffffffu, s, off);
        if (lane == 0) {
            float* dst = (mat == 0) ? bf : ((mat == 1) ? bs : lm);
            dst[row * NH + h] = s;
        }
    }
}
__global__ void beta_sig(float* bf, float* bs, float* lm, int n)
{
    int i = blockIdx.x * 256 + threadIdx.x;
    if (i >= n) return;
    float bb = bf[i], bd = bs[i], l = lm[i];
    bf[i] = 1.f / (1.f + expf(-(bb + bd)));
    bs[i] = 1.f / (1.f + expf(-(bb - bd)));
    lm[i] = 1.f / (1.f + expf(-l));
}

// =================== conv + SiLU (+l2norm) =================================
__global__ void conv_silu_norm(const float* __restrict__ qpre,
                               const float* __restrict__ kpre,
                               const float* __restrict__ vpre,
                               const float* __restrict__ cwq,
                               const float* __restrict__ cwk,
                               const float* __restrict__ cwv,
                               float* __restrict__ qo, float* __restrict__ ko,
                               float* __restrict__ vo)
{
    const int z = blockIdx.z;
    const float* pre = (z == 0) ? qpre : ((z == 1) ? kpre : vpre);
    const float* cw  = (z == 0) ? cwq  : ((z == 1) ? cwk  : cwv);
    float* out       = (z == 0) ? qo   : ((z == 1) ? ko   : vo);
    const int row = blockIdx.x;
    const int h   = blockIdx.y;
    const int t   = row & (TT - 1);
    const int c   = h * DKD + threadIdx.x;
    const size_t base = (size_t)row * HIDD + c;
    const float w0 = cw[c * 4 + 0], w1 = cw[c * 4 + 1];
    const float w2 = cw[c * 4 + 2], w3 = cw[c * 4 + 3];
    float y = w3 * pre[base];
    if (t >= 1) y += w2 * pre[base - HIDD];
    if (t >= 2) y += w1 * pre[base - 2 * HIDD];
    if (t >= 3) y += w0 * pre[base - 3 * HIDD];
    y = y / (1.f + expf(-y));
    if (z < 2) {
        __shared__ float red[4];
        float ss = y * y;
#pragma unroll
        for (int off = 16; off; off >>= 1) ss += __shfl_xor_sync(0xffffffffu, ss, off);
        if ((threadIdx.x & 31) == 0) red[threadIdx.x >> 5] = ss;
        __syncthreads();
        float tot = red[0] + red[1] + red[2] + red[3];
        float r = rsqrtf(tot + 1e-6f);
        if (z == 0) r *= 0.08838834764831845f;
        y *= r;
    }
    out[base] = y;
}

// =================== decay gates ===========================================
__global__ void gates_kernel(const float* __restrict__ A_log,
                             const float* __restrict__ dt_bias,
                             float* __restrict__ egf, float* __restrict__ egs)
{
    int idx = blockIdx.x * 256 + threadIdx.x;
    if (idx >= MROWS * HIDD) return;
    int c = idx & (HIDD - 1);
    int h = c >> 7;
    float gb = egf[idx], gd = egs[idx];
    float A  = expf(A_log[h]);
    float db = dt_bias[c];
    float xf = gb + gd + db, xs = gb - gd + db;
    float spf = (xf > 20.f) ? xf : log1pf(expf(xf));
    float sps = (xs > 20.f) ? xs : log1pf(expf(xs));
    egf[idx] = expf(-A * spf);
    egs[idx] = expf(-A * sps);
}

// =================== dual-state delta-rule recurrence ======================
__global__ void __launch_bounds__(128)
recurrence_kernel(const float* __restrict__ q, const float* __restrict__ k,
                  const float* __restrict__ v,
                  const float* __restrict__ egf, const float* __restrict__ egs,
                  const float* __restrict__ bfa, const float* __restrict__ bsa,
                  float* __restrict__ ost)
{
    const int s  = blockIdx.z >> 1;
    const int b  = blockIdx.z & 1;
    const int h  = blockIdx.y;
    const int vb = blockIdx.x;
    const int tid  = threadIdx.x;
    const int vloc = tid >> 2;
    const int sub  = tid & 3;
    const int vcol = vb * 32 + vloc;
    const int dk0  = sub * 32;
    const size_t rowbase = (size_t)b * TT * HIDD + h * DKD;
    const float* kp  = k   + rowbase + dk0;
    const float* qp  = q   + rowbase + dk0;
    const float* egp = ((s == 0) ? egf : egs) + rowbase + dk0;
    const float* vp  = v   + rowbase + vcol;
    const float* bp  = ((s == 0) ? bfa : bsa) + (size_t)b * TT * NH + h;
    float* op = ost + (size_t)s * MROWS * HIDD + rowbase + vcol;

    float S[32];
#pragma unroll
    for (int i = 0; i < 32; i++) S[i] = 0.f;

    for (int t = 0; t < TT; t++) {
        const size_t off = (size_t)t * HIDD;
        float kreg[32];
        float m0 = 0.f, m1 = 0.f, m2 = 0.f, m3 = 0.f;
#pragma unroll
        for (int i = 0; i < 32; i += 4) {
            float4 k4 = *(const float4*)(kp + off + i);
            float4 e4 = *(const float4*)(egp + off + i);
            float s0 = S[i + 0] * e4.x; S[i + 0] = s0;
            float s1 = S[i + 1] * e4.y; S[i + 1] = s1;
            float s2 = S[i + 2] * e4.z; S[i + 2] = s2;
            float s3 = S[i + 3] * e4.w; S[i + 3] = s3;
            kreg[i + 0] = k4.x; kreg[i + 1] = k4.y;
            kreg[i + 2] = k4.z; kreg[i + 3] = k4.w;
            m0 += k4.x * s0; m1 += k4.y * s1;
            m2 += k4.z * s2; m3 += k4.w * s3;
        }
        float mem = (m0 + m1) + (m2 + m3);
        mem += __shfl_xor_sync(0xffffffffu, mem, 1);
        mem += __shfl_xor_sync(0xffffffffu, mem, 2);
        const float beta = bp[(size_t)t * NH];
        const float vt   = vp[off];
        const float u    = beta * (vt - mem);
        float o0 = 0.f, o1 = 0.f, o2 = 0.f, o3 = 0.f;
#pragma unroll
        for (int i = 0; i < 32; i += 4) {
            float4 q4 = *(const float4*)(qp + off + i);
            float s0 = S[i + 0] + kreg[i + 0] * u; S[i + 0] = s0;
            float s1 = S[i + 1] + kreg[i + 1] * u; S[i + 1] = s1;
            float s2 = S[i + 2] + kreg[i + 2] * u; S[i + 2] = s2;
            float s3 = S[i + 3] + kreg[i + 3] * u; S[i + 3] = s3;
            o0 += q4.x * s0; o1 += q4.y * s1;
            o2 += q4.z * s2; o3 += q4.w * s3;
        }
        float o = (o0 + o1) + (o2 + o3);
        o += __shfl_xor_sync(0xffffffffu, o, 1);
        o += __shfl_xor_sync(0xffffffffu, o, 2);
        if (sub == 0) op[off] = o;
    }
}

// =================== mix + gated RMSNorm ===================================
__global__ void combine_kernel(const float* __restrict__ ost,
                               const float* __restrict__ lm,
                               const float* __restrict__ gate,
                               const float* __restrict__ onw,
                               float* __restrict__ omix)
{
    const int row = blockIdx.x;
    const int h   = blockIdx.y;
    const int dv  = threadIdx.x;
    const size_t i0 = (size_t)row * HIDD + h * DKD + dv;
    float of = ost[i0];
    float os = ost[(size_t)MROWS * HIDD + i0];
    float l  = lm[row * NH + h];
    float o  = l * of + (1.f - l) * os;
    __shared__ float red[4];
    float ss = o * o;
#pragma unroll
    for (int off = 16; off; off >>= 1) ss += __shfl_xor_sync(0xffffffffu, ss, off);
    if ((threadIdx.x & 31) == 0) red[threadIdx.x >> 5] = ss;
    __syncthreads();
    float tot = red[0] + red[1] + red[2] + red[3];
    float r = rsqrtf(tot * (1.f / 128.f) + 1e-5f);
    o = o * r * onw[dv];
    float g = gate[i0];
    o = o / (1.f + expf(-g));
    omix[i0] = o;
}

// =================== launch ================================================
extern "C" void kernel_launch(void* const* d_in, const int* in_sizes, int n_in,
                              void* d_out, int out_size)
{
    (void)in_sizes; (void)n_in; (void)out_size;
    const float* x    = (const float*)d_in[0];
    const float* Wq   = (const float*)d_in[1];
    const float* Wk   = (const float*)d_in[2];
    const float* Wv   = (const float*)d_in[3];
    const float* cwq  = (const float*)d_in[4];
    const float* cwk  = (const float*)d_in[5];
    const float* cwv  = (const float*)d_in[6];
    const float* Wgb1 = (const float*)d_in[7];
    const float* Wgb2 = (const float*)d_in[8];
    const float* Wgd1 = (const float*)d_in[9];
    const float* Wgd2 = (const float*)d_in[10];
    const float* Wbb  = (const float*)d_in[11];
    const float* Wbd  = (const float*)d_in[12];
    const float* Wlam = (const float*)d_in[13];
    const float* A_log= (const float*)d_in[14];
    const float* dtb  = (const float*)d_in[15];
    const float* Wg1  = (const float*)d_in[16];
    const float* Wg2  = (const float*)d_in[17];
    const float* bg2  = (const float*)d_in[18];
    const float* onw  = (const float*)d_in[19];
    const float* Wo   = (const float*)d_in[20];
    float* out = (float*)d_out;

    float *qpre, *kpre, *vpre, *q, *k, *v, *egf, *egs;
    float *gbp, *gdp, *g1p, *gate, *bfp, *bsp, *lmp, *ost, *omix;
    cudaGetSymbolAddress((void**)&qpre, g_qpre);
    cudaGetSymbolAddress((void**)&kpre, g_kpre);
    cudaGetSymbolAddress((void**)&vpre, g_vpre);
    cudaGetSymbolAddress((void**)&q,    g_q);
    cudaGetSymbolAddress((void**)&k,    g_k);
    cudaGetSymbolAddress((void**)&v,    g_v);
    cudaGetSymbolAddress((void**)&egf,  g_egf);
    cudaGetSymbolAddress((void**)&egs,  g_egs);
    cudaGetSymbolAddress((void**)&gbp,  g_gbp);
    cudaGetSymbolAddress((void**)&gdp,  g_gdp);
    cudaGetSymbolAddress((void**)&g1p,  g_g1p);
    cudaGetSymbolAddress((void**)&gate, g_gate);
    cudaGetSymbolAddress((void**)&bfp,  g_bf);
    cudaGetSymbolAddress((void**)&bsp,  g_bs);
    cudaGetSymbolAddress((void**)&lmp,  g_lm);
    cudaGetSymbolAddress((void**)&ost,  g_ost);
    cudaGetSymbolAddress((void**)&omix, g_omix);

    __nv_bfloat16 *xh, *xl, *oh, *ol, *p1h, *p1l;
    __nv_bfloat16 *WqkvTh, *WqkvTl, *WoTh, *WoTl, *W1Th, *W1Tl, *W2Th, *W2Tl;
    cudaGetSymbolAddress((void**)&xh, g_xh);
    cudaGetSymbolAddress((void**)&xl, g_xl);
    cudaGetSymbolAddress((void**)&oh, g_oh);
    cudaGetSymbolAddress((void**)&ol, g_ol);
    cudaGetSymbolAddress((void**)&p1h, g_p1h);
    cudaGetSymbolAddress((void**)&p1l, g_p1l);
    cudaGetSymbolAddress((void**)&WqkvTh, g_WqkvTh);
    cudaGetSymbolAddress((void**)&WqkvTl, g_WqkvTl);
    cudaGetSymbolAddress((void**)&WoTh, g_WoTh);
    cudaGetSymbolAddress((void**)&WoTl, g_WoTl);
    cudaGetSymbolAddress((void**)&W1Th, g_W1Th);
    cudaGetSymbolAddress((void**)&W1Tl, g_W1Tl);
    cudaGetSymbolAddress((void**)&W2Th, g_W2Th);
    cudaGetSymbolAddress((void**)&W2Tl, g_W2Tl);

    const size_t SQ = (size_t)HIDD * HIDD;
    const size_t SL = (size_t)128 * HIDD;
    const size_t SP = (size_t)MROWS * 128;

    // ---- hi/lo split of x
    convert_hilo<<<(MROWS * HIDD) / 1024, 256>>>(x, xh, xl, MROWS * HIDD);

    // ---- weight transposes + splits
    {
        TrArgs a; a.K = HIDD; a.N = HIDD;
        a.src[0] = Wq; a.src[1] = Wk; a.src[2] = Wv;
        a.dh[0] = WqkvTh; a.dh[1] = WqkvTh + SQ; a.dh[2] = WqkvTh + 2 * SQ;
        a.dl[0] = WqkvTl; a.dl[1] = WqkvTl + SQ; a.dl[2] = WqkvTl + 2 * SQ;
        transpose_hilo<<<dim3(64, 64, 3), dim3(32, 8)>>>(a);
    }
    {
        TrArgs a; a.K = HIDD; a.N = 128;
        a.src[0] = Wgb1; a.src[1] = Wgd1; a.src[2] = Wg1;
        a.dh[0] = W1Th; a.dh[1] = W1Th + SL; a.dh[2] = W1Th + 2 * SL;
        a.dl[0] = W1Tl; a.dl[1] = W1Tl + SL; a.dl[2] = W1Tl + 2 * SL;
        transpose_hilo<<<dim3(4, 64, 3), dim3(32, 8)>>>(a);
    }
    {
        TrArgs a; a.K = 128; a.N = HIDD;
        a.src[0] = Wgb2; a.src[1] = Wgd2; a.src[2] = Wg2;
        a.dh[0] = W2Th; a.dh[1] = W2Th + SL; a.dh[2] = W2Th + 2 * SL;
        a.dl[0] = W2Tl; a.dl[1] = W2Tl + SL; a.dl[2] = W2Tl + 2 * SL;
        transpose_hilo<<<dim3(64, 4, 3), dim3(32, 8)>>>(a);
    }
    {
        TrArgs a; a.K = HIDD; a.N = HIDD;
        a.src[0] = Wo; a.src[1] = Wo; a.src[2] = Wo;
        a.dh[0] = WoTh; a.dh[1] = WoTh; a.dh[2] = WoTh;
        a.dl[0] = WoTl; a.dl[1] = WoTl; a.dl[2] = WoTl;
        transpose_hilo<<<dim3(64, 64, 1), dim3(32, 8)>>>(a);
    }

    // ---- qkv projections
    {
        TcArgs a; a.M = MROWS; a.N = HIDD; a.K = HIDD;
        for (int i = 0; i < 3; i++) {
            a.Ah[i] = xh; a.Al[i] = xl;
            a.Bh[i] = WqkvTh + i * SQ; a.Bl[i] = WqkvTl + i * SQ;
            a.bias[i] = nullptr;
        }
        a.C[0] = qpre; a.C[1] = kpre; a.C[2] = vpre;
        hmma_gemm<<<dim3(16, 16, 3), 256>>>(a);
    }
    // ---- low-rank stage 1: N=128
    {
        TcArgs a; a.M = MROWS; a.N = 128; a.K = HIDD;
        for (int i = 0; i < 3; i++) {
            a.Ah[i] = xh; a.Al[i] = xl;
            a.Bh[i] = W1Th + i * SL; a.Bl[i] = W1Tl + i * SL;
            a.bias[i] = nullptr;
        }
        a.C[0] = gbp; a.C[1] = gdp; a.C[2] = g1p;
        hmma_gemm<<<dim3(1, 16, 3), 256>>>(a);
    }
    // ---- split stage-1 outputs
    convert_hilo<<<(int)(SP / 1024), 256>>>(gbp, p1h, p1l, (int)SP);
    convert_hilo<<<(int)(SP / 1024), 256>>>(gdp, p1h + SP, p1l + SP, (int)SP);
    convert_hilo<<<(int)(SP / 1024), 256>>>(g1p, p1h + 2 * SP, p1l + 2 * SP, (int)SP);
    // ---- low-rank stage 2: K=128
    {
        TcArgs a; a.M = MROWS; a.N = HIDD; a.K = 128;
        for (int i = 0; i < 3; i++) {
            a.Ah[i] = p1h + i * SP; a.Al[i] = p1l + i * SP;
            a.Bh[i] = W2Th + i * SL; a.Bl[i] = W2Tl + i * SL;
            a.bias[i] = nullptr;
        }
        a.bias[2] = bg2;
        a.C[0] = egf; a.C[1] = egs; a.C[2] = gate;
        hmma_gemm<<<dim3(16, 16, 3), 256>>>(a);
    }
    // ---- betas / lambda
    beta_dots<<<MROWS, 256>>>(x, Wbb, Wbd, Wlam, bfp, bsp, lmp);
    beta_sig<<<(MROWS * NH + 255) / 256, 256>>>(bfp, bsp, lmp, MROWS * NH);
    // ---- conv + silu + l2norm
    conv_silu_norm<<<dim3(MROWS, NH, 3), 128>>>(qpre, kpre, vpre, cwq, cwk, cwv, q, k, v);
    // ---- decay gates
    gates_kernel<<<(MROWS * HIDD) / 256, 256>>>(A_log, dtb, egf, egs);
    // ---- recurrence
    recurrence_kernel<<<dim3(4, NH, 4), 128>>>(q, k, v, egf, egs, bfp, bsp, ost);
    // ---- mix + gated rmsnorm
    combine_kernel<<<dim3(MROWS, NH), 128>>>(ost, lmp, gate, onw, omix);
    // ---- output projection
    convert_hilo<<<(MROWS * HIDD) / 1024, 256>>>(omix, oh, ol, MROWS * HIDD);
    {
        TcArgs a; a.M = MROWS; a.N = HIDD; a.K = HIDD;
        for (int i = 0; i < 3; i++) {
            a.Ah[i] = oh; a.Al[i] = ol; a.Bh[i] = WoTh; a.Bl[i] = WoTl;
            a.bias[i] = nullptr; a.C[i] = out;
        }
        hmma_gemm<<<dim3(16, 16, 1), 256>>>(a);
    }
}

// round 4
// speedup vs baseline: 1.5286x; 1.0407x over previous
#include <cuda_runtime.h>
#include <cuda_bf16.h>
#include <math.h>
#include <stdint.h>

#define BQ    2
#define TT    1024
#define HIDD  2048
#define NH    16
#define DKD   128
#define DVD   128
#define MROWS 2048   // BQ*TT

// =================== scratch (device globals; no allocation) ===============
__device__ __align__(16) float g_qpre[MROWS * HIDD];
__device__ __align__(16) float g_kpre[MROWS * HIDD];
__device__ __align__(16) float g_vpre[MROWS * HIDD];
__device__ __align__(16) float g_q[MROWS * HIDD];
__device__ __align__(16) float g_k[MROWS * HIDD];
__device__ __align__(16) float g_v[MROWS * HIDD];
__device__ __align__(16) float g_egf[MROWS * HIDD];
__device__ __align__(16) float g_egs[MROWS * HIDD];
__device__ __align__(16) float g_gbp[MROWS * 128];
__device__ __align__(16) float g_gdp[MROWS * 128];
__device__ __align__(16) float g_g1p[MROWS * 128];
__device__ __align__(16) float g_gate[MROWS * HIDD];
__device__ __align__(16) float g_bf[MROWS * NH];
__device__ __align__(16) float g_bs[MROWS * NH];
__device__ __align__(16) float g_lm[MROWS * NH];
__device__ __align__(16) float g_ost[2 * MROWS * HIDD];
__device__ __align__(16) float g_omix[MROWS * HIDD];

// bf16 hi/lo splits
__device__ __align__(16) __nv_bfloat16 g_xh[MROWS * HIDD];
__device__ __align__(16) __nv_bfloat16 g_xl[MROWS * HIDD];
__device__ __align__(16) __nv_bfloat16 g_oh[MROWS * HIDD];
__device__ __align__(16) __nv_bfloat16 g_ol[MROWS * HIDD];
__device__ __align__(16) __nv_bfloat16 g_p1h[3][MROWS * 128];
__device__ __align__(16) __nv_bfloat16 g_p1l[3][MROWS * 128];
// transposed weights [N,K] hi/lo
__device__ __align__(16) __nv_bfloat16 g_WqkvTh[3][HIDD * HIDD];
__device__ __align__(16) __nv_bfloat16 g_WqkvTl[3][HIDD * HIDD];
__device__ __align__(16) __nv_bfloat16 g_WoTh[HIDD * HIDD];
__device__ __align__(16) __nv_bfloat16 g_WoTl[HIDD * HIDD];
__device__ __align__(16) __nv_bfloat16 g_W1Th[3][128 * HIDD];
__device__ __align__(16) __nv_bfloat16 g_W1Tl[3][128 * HIDD];
__device__ __align__(16) __nv_bfloat16 g_W2Th[3][HIDD * 128];
__device__ __align__(16) __nv_bfloat16 g_W2Tl[3][HIDD * 128];

// =================== warp-MMA primitives ===================================
__device__ __forceinline__ void mma16816(float* c, const uint32_t* a, const uint32_t* b) {
    asm volatile(
        "mma.sync.aligned.m16n8k16.row.col.f32.bf16.bf16.f32 "
        "{%0,%1,%2,%3}, {%4,%5,%6,%7}, {%8,%9}, {%0,%1,%2,%3};"
        : "+f"(c[0]), "+f"(c[1]), "+f"(c[2]), "+f"(c[3])
        : "r"(a[0]), "r"(a[1]), "r"(a[2]), "r"(a[3]), "r"(b[0]), "r"(b[1]));
}
__device__ __forceinline__ void ldsm_x4(uint32_t* r, uint32_t addr) {
    asm volatile("ldmatrix.sync.aligned.m8n8.x4.shared.b16 {%0,%1,%2,%3}, [%4];"
                 : "=r"(r[0]), "=r"(r[1]), "=r"(r[2]), "=r"(r[3]) : "r"(addr));
}
#define CPA16(dst, src) \
    asm volatile("cp.async.cg.shared.global [%0], [%1], 16;" :: "r"(dst), "l"(src))
#define CPA_COMMIT() asm volatile("cp.async.commit_group;" ::: "memory")
#define CPA_WAIT1()  asm volatile("cp.async.wait_group 1;" ::: "memory")

// =================== compensated-bf16 HMMA GEMM (double-buffered) ==========
// C[z] = A[z][M,K] @ B[z][N,K]^T. 3 passes AhBh + AhBl + AlBh.
// BM = MI*32 (MI=4 -> 128, MI=2 -> 64), BN = 128, BK = 32.
// 8 warps: 2 (m) x 4 (n); warp tile (MI*16) x 32.
struct TcArgs {
    const __nv_bfloat16 *Ah[3], *Al[3], *Bh[3], *Bl[3];
    float *C[3];
    const float *bias[3];
    int M, N, K;
};

#define TSTRIDE 40   // 32 + 8 pad: conflict-free ldmatrix

template<int MI>
__global__ void __launch_bounds__(256, 2) hmma_gemm(const TcArgs args)
{
    constexpr int BM  = MI * 32;
    constexpr int ASZ = BM * TSTRIDE * 2;    // bytes per A buffer
    constexpr int BSZ = 128 * TSTRIDE * 2;   // bytes per B buffer

    extern __shared__ __align__(16) char smem[];
    const uint32_t base = (uint32_t)__cvta_generic_to_shared(smem);
    const uint32_t AhU = base;
    const uint32_t AlU = base + 2 * ASZ;
    const uint32_t BhU = base + 4 * ASZ;
    const uint32_t BlU = base + 4 * ASZ + 2 * BSZ;

    const int tid  = threadIdx.x;
    const int wid  = tid >> 5, lane = tid & 31;
    const int wm   = wid >> 2;
    const int wn   = wid & 3;
    const int z    = blockIdx.z;
    const int bm   = blockIdx.y * BM, bn = blockIdx.x * 128;
    const int K    = args.K;
    const __nv_bfloat16* Ah = args.Ah[z];
    const __nv_bfloat16* Al = args.Al[z];
    const __nv_bfloat16* Bh = args.Bh[z];
    const __nv_bfloat16* Bl = args.Bl[z];

    float C[MI][4][4];
#pragma unroll
    for (int i = 0; i < MI; i++)
#pragma unroll
        for (int j = 0; j < 4; j++)
#pragma unroll
            for (int e = 0; e < 4; e++) C[i][j][e] = 0.f;

    const int a_r = (lane & 15);
    const int a_c = (lane >> 4) << 3;
    const int b_r = (lane & 7) + ((lane >> 4) << 3);
    const int b_c = ((lane >> 3) & 1) << 3;

    const int nch = K >> 5;

    auto load_stage = [&](int buf, int k0) {
#pragma unroll 2
        for (int idx = tid; idx < BM * 4; idx += 256) {
            const int row = idx >> 2, c16 = (idx & 3) * 8;
            const uint32_t so = (uint32_t)(row * TSTRIDE + c16) * 2 + buf * ASZ;
            const size_t g = (size_t)(bm + row) * K + k0 + c16;
            CPA16(AhU + so, Ah + g);
            CPA16(AlU + so, Al + g);
        }
#pragma unroll 2
        for (int idx = tid; idx < 512; idx += 256) {
            const int row = idx >> 2, c16 = (idx & 3) * 8;
            const uint32_t so = (uint32_t)(row * TSTRIDE + c16) * 2 + buf * BSZ;
            const size_t g = (size_t)(bn + row) * K + k0 + c16;
            CPA16(BhU + so, Bh + g);
            CPA16(BlU + so, Bl + g);
        }
    };

    // prologue: fill both stages
    load_stage(0, 0);
    CPA_COMMIT();
    if (nch > 1) load_stage(1, 32);
    CPA_COMMIT();

    for (int ch = 0; ch < nch; ch++) {
        CPA_WAIT1();
        __syncthreads();
        const int buf = ch & 1;
        const uint32_t aho = AhU + buf * ASZ, alo = AlU + buf * ASZ;
        const uint32_t bho = BhU + buf * BSZ, blo = BlU + buf * BSZ;
#pragma unroll
        for (int kk = 0; kk < 32; kk += 16) {
            uint32_t afh[MI][4], bfh[2][4], bfl[2][4];
#pragma unroll
            for (int mi = 0; mi < MI; mi++) {
                const int r = wm * (MI * 16) + mi * 16 + a_r;
                ldsm_x4(afh[mi], aho + (uint32_t)(r * TSTRIDE + kk + a_c) * 2);
            }
#pragma unroll
            for (int nb = 0; nb < 2; nb++) {
                const int r = wn * 32 + nb * 16 + b_r;
                ldsm_x4(bfh[nb], bho + (uint32_t)(r * TSTRIDE + kk + b_c) * 2);
                ldsm_x4(bfl[nb], blo + (uint32_t)(r * TSTRIDE + kk + b_c) * 2);
            }
#pragma unroll
            for (int mi = 0; mi < MI; mi++)
#pragma unroll
                for (int nj = 0; nj < 4; nj++)
                    mma16816(C[mi][nj], afh[mi], &bfh[nj >> 1][(nj & 1) * 2]);
#pragma unroll
            for (int mi = 0; mi < MI; mi++)
#pragma unroll
                for (int nj = 0; nj < 4; nj++)
                    mma16816(C[mi][nj], afh[mi], &bfl[nj >> 1][(nj & 1) * 2]);
            uint32_t afl[MI][4];
#pragma unroll
            for (int mi = 0; mi < MI; mi++) {
                const int r = wm * (MI * 16) + mi * 16 + a_r;
                ldsm_x4(afl[mi], alo + (uint32_t)(r * TSTRIDE + kk + a_c) * 2);
            }
#pragma unroll
            for (int mi = 0; mi < MI; mi++)
#pragma unroll
                for (int nj = 0; nj < 4; nj++)
                    mma16816(C[mi][nj], afl[mi], &bfh[nj >> 1][(nj & 1) * 2]);
        }
        __syncthreads();
        if (ch + 2 < nch) load_stage(buf, (ch + 2) * 32);
        CPA_COMMIT();
    }

    // epilogue
    float* Cg = args.C[z];
    const float* bias = args.bias[z];
    const int N = args.N;
#pragma unroll
    for (int mi = 0; mi < MI; mi++) {
#pragma unroll
        for (int nj = 0; nj < 4; nj++) {
            const int r0 = bm + wm * (MI * 16) + mi * 16 + (lane >> 2);
            const int c0 = bn + wn * 32 + nj * 8 + (lane & 3) * 2;
            float v0 = C[mi][nj][0], v1 = C[mi][nj][1];
            float v2 = C[mi][nj][2], v3 = C[mi][nj][3];
            if (bias) {
                const float b0 = bias[c0], b1 = bias[c0 + 1];
                v0 += b0; v1 += b1; v2 += b0; v3 += b1;
            }
            *(float2*)(Cg + (size_t)r0 * N + c0)       = make_float2(v0, v1);
            *(float2*)(Cg + (size_t)(r0 + 8) * N + c0) = make_float2(v2, v3);
        }
    }
}

#define SMEM_MI4 (4 * (128 * TSTRIDE * 2) + 4 * (128 * TSTRIDE * 2))
#define SMEM_MI2 (4 * (64  * TSTRIDE * 2) + 4 * (128 * TSTRIDE * 2))

// =================== hi/lo split (elementwise) =============================
__global__ void convert_hilo(const float* __restrict__ s,
                             __nv_bfloat16* __restrict__ h,
                             __nv_bfloat16* __restrict__ l, int n)
{
    int i = (blockIdx.x * 256 + threadIdx.x) * 4;
    if (i >= n) return;
    float4 v = *(const float4*)(s + i);
    __nv_bfloat16 h0 = __float2bfloat16(v.x), h1 = __float2bfloat16(v.y);
    __nv_bfloat16 h2 = __float2bfloat16(v.z), h3 = __float2bfloat16(v.w);
    __nv_bfloat162 hh0; hh0.x = h0; hh0.y = h1;
    __nv_bfloat162 hh1; hh1.x = h2; hh1.y = h3;
    *(__nv_bfloat162*)(h + i)     = hh0;
    *(__nv_bfloat162*)(h + i + 2) = hh1;
    __nv_bfloat162 ll0, ll1;
    ll0.x = __float2bfloat16(v.x - __bfloat162float(h0));
    ll0.y = __float2bfloat16(v.y - __bfloat162float(h1));
    ll1.x = __float2bfloat16(v.z - __bfloat162float(h2));
    ll1.y = __float2bfloat16(v.w - __bfloat162float(h3));
    *(__nv_bfloat162*)(l + i)     = ll0;
    *(__nv_bfloat162*)(l + i + 2) = ll1;
}

// =================== transpose + hi/lo split: W[K,N] -> Bt[N,K] ============
struct TrArgs {
    const float* src[3];
    __nv_bfloat16 *dh[3], *dl[3];
    int K, N;
};
__global__ void transpose_hilo(const TrArgs a)
{
    __shared__ float tile[32][33];
    const float* W = a.src[blockIdx.z];
    __nv_bfloat16* dh = a.dh[blockIdx.z];
    __nv_bfloat16* dl = a.dl[blockIdx.z];
    const int n0 = blockIdx.x * 32, k0 = blockIdx.y * 32;
    const int tx = threadIdx.x, ty = threadIdx.y;
#pragma unroll
    for (int i = 0; i < 32; i += 8)
        tile[ty + i][tx] = W[(size_t)(k0 + ty + i) * a.N + n0 + tx];
    __syncthreads();
#pragma unroll
    for (int i = 0; i < 32; i += 8) {
        float v = tile[tx][ty + i];
        __nv_bfloat16 h = __float2bfloat16(v);
        size_t o = (size_t)(n0 + ty + i) * a.K + k0 + tx;
        dh[o] = h;
        dl[o] = __float2bfloat16(v - __bfloat162float(h));
    }
}

// =================== bb/bd/lam skinny dots =================================
__global__ void beta_dots(const float* __restrict__ x,
                          const float* __restrict__ Wbb,
                          const float* __restrict__ Wbd,
                          const float* __restrict__ Wlam,
                          float* __restrict__ bf, float* __restrict__ bs,
                          float* __restrict__ lm)
{
    __shared__ float xs[HIDD];
    const int row = blockIdx.x;
    const float* xr = x + (size_t)row * HIDD;
    for (int i = threadIdx.x; i < HIDD; i += 256) xs[i] = xr[i];
    __syncthreads();
    const int w = threadIdx.x >> 5, lane = threadIdx.x & 31;
    for (int d = w; d < 48; d += 8) {
        const int mat = d >> 4, h = d & 15;
        const float* W = (mat == 0) ? Wbb : ((mat == 1) ? Wbd : Wlam);
        float s = 0.f;
        for (int i = lane; i < HIDD; i += 32) s += xs[i] * W[(size_t)i * NH + h];
#pragma unroll
        for (int off = 16; off; off >>= 1) s += __shfl_xor_sync(0xffffffffu, s, off);
        if (lane == 0) {
            float* dst = (mat == 0) ? bf : ((mat == 1) ? bs : lm);
            dst[row * NH + h] = s;
        }
    }
}
__global__ void beta_sig(float* bf, float* bs, float* lm, int n)
{
    int i = blockIdx.x * 256 + threadIdx.x;
    if (i >= n) return;
    float bb = bf[i], bd = bs[i], l = lm[i];
    bf[i] = 1.f / (1.f + expf(-(bb + bd)));
    bs[i] = 1.f / (1.f + expf(-(bb - bd)));
    lm[i] = 1.f / (1.f + expf(-l));
}

// =================== conv + SiLU (+l2norm) =================================
__global__ void conv_silu_norm(const float* __restrict__ qpre,
                               const float* __restrict__ kpre,
                               const float* __restrict__ vpre,
                               const float* __restrict__ cwq,
                               const float* __restrict__ cwk,
                               const float* __restrict__ cwv,
                               float* __restrict__ qo, float* __restrict__ ko,
                               float* __restrict__ vo)
{
    const int z = blockIdx.z;
    const float* pre = (z == 0) ? qpre : ((z == 1) ? kpre : vpre);
    const float* cw  = (z == 0) ? cwq  : ((z == 1) ? cwk  : cwv);
    float* out       = (z == 0) ? qo   : ((z == 1) ? ko   : vo);
    const int row = blockIdx.x;
    const int h   = blockIdx.y;
    const int t   = row & (TT - 1);
    const int c   = h * DKD + threadIdx.x;
    const size_t base = (size_t)row * HIDD + c;
    const float w0 = cw[c * 4 + 0], w1 = cw[c * 4 + 1];
    const float w2 = cw[c * 4 + 2], w3 = cw[c * 4 + 3];
    float y = w3 * pre[base];
    if (t >= 1) y += w2 * pre[base - HIDD];
    if (t >= 2) y += w1 * pre[base - 2 * HIDD];
    if (t >= 3) y += w0 * pre[base - 3 * HIDD];
    y = y / (1.f + expf(-y));
    if (z < 2) {
        __shared__ float red[4];
        float ss = y * y;
#pragma unroll
        for (int off = 16; off; off >>= 1) ss += __shfl_xor_sync(0xffffffffu, ss, off);
        if ((threadIdx.x & 31) == 0) red[threadIdx.x >> 5] = ss;
        __syncthreads();
        float tot = red[0] + red[1] + red[2] + red[3];
        float r = rsqrtf(tot + 1e-6f);
        if (z == 0) r *= 0.08838834764831845f;
        y *= r;
    }
    out[base] = y;
}

// =================== decay gates ===========================================
__global__ void gates_kernel(const float* __restrict__ A_log,
                             const float* __restrict__ dt_bias,
                             float* __restrict__ egf, float* __restrict__ egs)
{
    int idx = blockIdx.x * 256 + threadIdx.x;
    if (idx >= MROWS * HIDD) return;
    int c = idx & (HIDD - 1);
    int h = c >> 7;
    float gb = egf[idx], gd = egs[idx];
    float A  = expf(A_log[h]);
    float db = dt_bias[c];
    float xf = gb + gd + db, xs = gb - gd + db;
    float spf = (xf > 20.f) ? xf : log1pf(expf(xf));
    float sps = (xs > 20.f) ? xs : log1pf(expf(xs));
    egf[idx] = expf(-A * spf);
    egs[idx] = expf(-A * sps);
}

// =================== dual-state delta-rule recurrence ======================
__global__ void __launch_bounds__(128)
recurrence_kernel(const float* __restrict__ q, const float* __restrict__ k,
                  const float* __restrict__ v,
                  const float* __restrict__ egf, const float* __restrict__ egs,
                  const float* __restrict__ bfa, const float* __restrict__ bsa,
                  float* __restrict__ ost)
{
    const int s  = blockIdx.z >> 1;
    const int b  = blockIdx.z & 1;
    const int h  = blockIdx.y;
    const int vb = blockIdx.x;
    const int tid  = threadIdx.x;
    const int vloc = tid >> 2;
    const int sub  = tid & 3;
    const int vcol = vb * 32 + vloc;
    const int dk0  = sub * 32;
    const size_t rowbase = (size_t)b * TT * HIDD + h * DKD;
    const float* kp  = k   + rowbase + dk0;
    const float* qp  = q   + rowbase + dk0;
    const float* egp = ((s == 0) ? egf : egs) + rowbase + dk0;
    const float* vp  = v   + rowbase + vcol;
    const float* bp  = ((s == 0) ? bfa : bsa) + (size_t)b * TT * NH + h;
    float* op = ost + (size_t)s * MROWS * HIDD + rowbase + vcol;

    float S[32];
#pragma unroll
    for (int i = 0; i < 32; i++) S[i] = 0.f;

    for (int t = 0; t < TT; t++) {
        const size_t off = (size_t)t * HIDD;
        float kreg[32];
        float m0 = 0.f, m1 = 0.f, m2 = 0.f, m3 = 0.f;
#pragma unroll
        for (int i = 0; i < 32; i += 4) {
            float4 k4 = *(const float4*)(kp + off + i);
            float4 e4 = *(const float4*)(egp + off + i);
            float s0 = S[i + 0] * e4.x; S[i + 0] = s0;
            float s1 = S[i + 1] * e4.y; S[i + 1] = s1;
            float s2 = S[i + 2] * e4.z; S[i + 2] = s2;
            float s3 = S[i + 3] * e4.w; S[i + 3] = s3;
            kreg[i + 0] = k4.x; kreg[i + 1] = k4.y;
            kreg[i + 2] = k4.z; kreg[i + 3] = k4.w;
            m0 += k4.x * s0; m1 += k4.y * s1;
            m2 += k4.z * s2; m3 += k4.w * s3;
        }
        float mem = (m0 + m1) + (m2 + m3);
        mem += __shfl_xor_sync(0xffffffffu, mem, 1);
        mem += __shfl_xor_sync(0xffffffffu, mem, 2);
        const float beta = bp[(size_t)t * NH];
        const float vt   = vp[off];
        const float u    = beta * (vt - mem);
        float o0 = 0.f, o1 = 0.f, o2 = 0.f, o3 = 0.f;
#pragma unroll
        for (int i = 0; i < 32; i += 4) {
            float4 q4 = *(const float4*)(qp + off + i);
            float s0 = S[i + 0] + kreg[i + 0] * u; S[i + 0] = s0;
            float s1 = S[i + 1] + kreg[i + 1] * u; S[i + 1] = s1;
            float s2 = S[i + 2] + kreg[i + 2] * u; S[i + 2] = s2;
            float s3 = S[i + 3] + kreg[i + 3] * u; S[i + 3] = s3;
            o0 += q4.x * s0; o1 += q4.y * s1;
            o2 += q4.z * s2; o3 += q4.w * s3;
        }
        float o = (o0 + o1) + (o2 + o3);
        o += __shfl_xor_sync(0xffffffffu, o, 1);
        o += __shfl_xor_sync(0xffffffffu, o, 2);
        if (sub == 0) op[off] = o;
    }
}

// =================== mix + gated RMSNorm ===================================
__global__ void combine_kernel(const float* __restrict__ ost,
                               const float* __restrict__ lm,
                               const float* __restrict__ gate,
                               const float* __restrict__ onw,
                               float* __restrict__ omix)
{
    const int row = blockIdx.x;
    const int h   = blockIdx.y;
    const int dv  = threadIdx.x;
    const size_t i0 = (size_t)row * HIDD + h * DKD + dv;
    float of = ost[i0];
    float os = ost[(size_t)MROWS * HIDD + i0];
    float l  = lm[row * NH + h];
    float o  = l * of + (1.f - l) * os;
    __shared__ float red[4];
    float ss = o * o;
#pragma unroll
    for (int off = 16; off; off >>= 1) ss += __shfl_xor_sync(0xffffffffu, ss, off);
    if ((threadIdx.x & 31) == 0) red[threadIdx.x >> 5] = ss;
    __syncthreads();
    float tot = red[0] + red[1] + red[2] + red[3];
    float r = rsqrtf(tot * (1.f / 128.f) + 1e-5f);
    o = o * r * onw[dv];
    float g = gate[i0];
    o = o / (1.f + expf(-g));
    omix[i0] = o;
}

// =================== launch ================================================
extern "C" void kernel_launch(void* const* d_in, const int* in_sizes, int n_in,
                              void* d_out, int out_size)
{
    (void)in_sizes; (void)n_in; (void)out_size;
    const float* x    = (const float*)d_in[0];
    const float* Wq   = (const float*)d_in[1];
    const float* Wk   = (const float*)d_in[2];
    const float* Wv   = (const float*)d_in[3];
    const float* cwq  = (const float*)d_in[4];
    const float* cwk  = (const float*)d_in[5];
    const float* cwv  = (const float*)d_in[6];
    const float* Wgb1 = (const float*)d_in[7];
    const float* Wgb2 = (const float*)d_in[8];
    const float* Wgd1 = (const float*)d_in[9];
    const float* Wgd2 = (const float*)d_in[10];
    const float* Wbb  = (const float*)d_in[11];
    const float* Wbd  = (const float*)d_in[12];
    const float* Wlam = (const float*)d_in[13];
    const float* A_log= (const float*)d_in[14];
    const float* dtb  = (const float*)d_in[15];
    const float* Wg1  = (const float*)d_in[16];
    const float* Wg2  = (const float*)d_in[17];
    const float* bg2  = (const float*)d_in[18];
    const float* onw  = (const float*)d_in[19];
    const float* Wo   = (const float*)d_in[20];
    float* out = (float*)d_out;

    float *qpre, *kpre, *vpre, *q, *k, *v, *egf, *egs;
    float *gbp, *gdp, *g1p, *gate, *bfp, *bsp, *lmp, *ost, *omix;
    cudaGetSymbolAddress((void**)&qpre, g_qpre);
    cudaGetSymbolAddress((void**)&kpre, g_kpre);
    cudaGetSymbolAddress((void**)&vpre, g_vpre);
    cudaGetSymbolAddress((void**)&q,    g_q);
    cudaGetSymbolAddress((void**)&k,    g_k);
    cudaGetSymbolAddress((void**)&v,    g_v);
    cudaGetSymbolAddress((void**)&egf,  g_egf);
    cudaGetSymbolAddress((void**)&egs,  g_egs);
    cudaGetSymbolAddress((void**)&gbp,  g_gbp);
    cudaGetSymbolAddress((void**)&gdp,  g_gdp);
    cudaGetSymbolAddress((void**)&g1p,  g_g1p);
    cudaGetSymbolAddress((void**)&gate, g_gate);
    cudaGetSymbolAddress((void**)&bfp,  g_bf);
    cudaGetSymbolAddress((void**)&bsp,  g_bs);
    cudaGetSymbolAddress((void**)&lmp,  g_lm);
    cudaGetSymbolAddress((void**)&ost,  g_ost);
    cudaGetSymbolAddress((void**)&omix, g_omix);

    __nv_bfloat16 *xh, *xl, *oh, *ol, *p1h, *p1l;
    __nv_bfloat16 *WqkvTh, *WqkvTl, *WoTh, *WoTl, *W1Th, *W1Tl, *W2Th, *W2Tl;
    cudaGetSymbolAddress((void**)&xh, g_xh);
    cudaGetSymbolAddress((void**)&xl, g_xl);
    cudaGetSymbolAddress((void**)&oh, g_oh);
    cudaGetSymbolAddress((void**)&ol, g_ol);
    cudaGetSymbolAddress((void**)&p1h, g_p1h);
    cudaGetSymbolAddress((void**)&p1l, g_p1l);
    cudaGetSymbolAddress((void**)&WqkvTh, g_WqkvTh);
    cudaGetSymbolAddress((void**)&WqkvTl, g_WqkvTl);
    cudaGetSymbolAddress((void**)&WoTh, g_WoTh);
    cudaGetSymbolAddress((void**)&WoTl, g_WoTl);
    cudaGetSymbolAddress((void**)&W1Th, g_W1Th);
    cudaGetSymbolAddress((void**)&W1Tl, g_W1Tl);
    cudaGetSymbolAddress((void**)&W2Th, g_W2Th);
    cudaGetSymbolAddress((void**)&W2Tl, g_W2Tl);

    cudaFuncSetAttribute(hmma_gemm<4>, cudaFuncAttributeMaxDynamicSharedMemorySize, SMEM_MI4);
    cudaFuncSetAttribute(hmma_gemm<2>, cudaFuncAttributeMaxDynamicSharedMemorySize, SMEM_MI2);

    const size_t SQ = (size_t)HIDD * HIDD;
    const size_t SL = (size_t)128 * HIDD;
    const size_t SP = (size_t)MROWS * 128;

    // ---- hi/lo split of x
    convert_hilo<<<(MROWS * HIDD) / 1024, 256>>>(x, xh, xl, MROWS * HIDD);

    // ---- weight transposes + splits
    {
        TrArgs a; a.K = HIDD; a.N = HIDD;
        a.src[0] = Wq; a.src[1] = Wk; a.src[2] = Wv;
        a.dh[0] = WqkvTh; a.dh[1] = WqkvTh + SQ; a.dh[2] = WqkvTh + 2 * SQ;
        a.dl[0] = WqkvTl; a.dl[1] = WqkvTl + SQ; a.dl[2] = WqkvTl + 2 * SQ;
        transpose_hilo<<<dim3(64, 64, 3), dim3(32, 8)>>>(a);
    }
    {
        TrArgs a; a.K = HIDD; a.N = 128;
        a.src[0] = Wgb1; a.src[1] = Wgd1; a.src[2] = Wg1;
        a.dh[0] = W1Th; a.dh[1] = W1Th + SL; a.dh[2] = W1Th + 2 * SL;
        a.dl[0] = W1Tl; a.dl[1] = W1Tl + SL; a.dl[2] = W1Tl + 2 * SL;
        transpose_hilo<<<dim3(4, 64, 3), dim3(32, 8)>>>(a);
    }
    {
        TrArgs a; a.K = 128; a.N = HIDD;
        a.src[0] = Wgb2; a.src[1] = Wgd2; a.src[2] = Wg2;
        a.dh[0] = W2Th; a.dh[1] = W2Th + SL; a.dh[2] = W2Th + 2 * SL;
        a.dl[0] = W2Tl; a.dl[1] = W2Tl + SL; a.dl[2] = W2Tl + 2 * SL;
        transpose_hilo<<<dim3(64, 4, 3), dim3(32, 8)>>>(a);
    }
    {
        TrArgs a; a.K = HIDD; a.N = HIDD;
        a.src[0] = Wo; a.src[1] = Wo; a.src[2] = Wo;
        a.dh[0] = WoTh; a.dh[1] = WoTh; a.dh[2] = WoTh;
        a.dl[0] = WoTl; a.dl[1] = WoTl; a.dl[2] = WoTl;
        transpose_hilo<<<dim3(64, 64, 1), dim3(32, 8)>>>(a);
    }

    // ---- qkv projections
    {
        TcArgs a; a.M = MROWS; a.N = HIDD; a.K = HIDD;
        for (int i = 0; i < 3; i++) {
            a.Ah[i] = xh; a.Al[i] = xl;
            a.Bh[i] = WqkvTh + i * SQ; a.Bl[i] = WqkvTl + i * SQ;
            a.bias[i] = nullptr;
        }
        a.C[0] = qpre; a.C[1] = kpre; a.C[2] = vpre;
        hmma_gemm<4><<<dim3(16, 16, 3), 256, SMEM_MI4>>>(a);
    }
    // ---- low-rank stage 1: N=128 (BM=64 variant for grid fill)
    {
        TcArgs a; a.M = MROWS; a.N = 128; a.K = HIDD;
        for (int i = 0; i < 3; i++) {
            a.Ah[i] = xh; a.Al[i] = xl;
            a.Bh[i] = W1Th + i * SL; a.Bl[i] = W1Tl + i * SL;
            a.bias[i] = nullptr;
        }
        a.C[0] = gbp; a.C[1] = gdp; a.C[2] = g1p;
        hmma_gemm<2><<<dim3(1, 32, 3), 256, SMEM_MI2>>>(a);
    }
    // ---- split stage-1 outputs
    convert_hilo<<<(int)(SP / 1024), 256>>>(gbp, p1h, p1l, (int)SP);
    convert_hilo<<<(int)(SP / 1024), 256>>>(gdp, p1h + SP, p1l + SP, (int)SP);
    convert_hilo<<<(int)(SP / 1024), 256>>>(g1p, p1h + 2 * SP, p1l + 2 * SP, (int)SP);
    // ---- low-rank stage 2: K=128
    {
        TcArgs a; a.M = MROWS; a.N = HIDD; a.K = 128;
        for (int i = 0; i < 3; i++) {
            a.Ah[i] = p1h + i * SP; a.Al[i] = p1l + i * SP;
            a.Bh[i] = W2Th + i * SL; a.Bl[i] = W2Tl + i * SL;
            a.bias[i] = nullptr;
        }
        a.bias[2] = bg2;
        a.C[0] = egf; a.C[1] = egs; a.C[2] = gate;
        hmma_gemm<4><<<dim3(16, 16, 3), 256, SMEM_MI4>>>(a);
    }
    // ---- betas / lambda
    beta_dots<<<MROWS, 256>>>(x, Wbb, Wbd, Wlam, bfp, bsp, lmp);
    beta_sig<<<(MROWS * NH + 255) / 256, 256>>>(bfp, bsp, lmp, MROWS * NH);
    // ---- conv + silu + l2norm
    conv_silu_norm<<<dim3(MROWS, NH, 3), 128>>>(qpre, kpre, vpre, cwq, cwk, cwv, q, k, v);
    // ---- decay gates
    gates_kernel<<<(MROWS * HIDD) / 256, 256>>>(A_log, dtb, egf, egs);
    // ---- recurrence
    recurrence_kernel<<<dim3(4, NH, 4), 128>>>(q, k, v, egf, egs, bfp, bsp, ost);
    // ---- mix + gated rmsnorm
    combine_kernel<<<dim3(MROWS, NH), 128>>>(ost, lmp, gate, onw, omix);
    // ---- output projection
    convert_hilo<<<(MROWS * HIDD) / 1024, 256>>>(omix, oh, ol, MROWS * HIDD);
    {
        TcArgs a; a.M = MROWS; a.N = HIDD; a.K = HIDD;
        for (int i = 0; i < 3; i++) {
            a.Ah[i] = oh; a.Al[i] = ol; a.Bh[i] = WoTh; a.Bl[i] = WoTl;
            a.bias[i] = nullptr; a.C[i] = out;
        }
        hmma_gemm<4><<<dim3(16, 16, 1), 256, SMEM_MI4>>>(a);
    }
}